// round 8
// baseline (speedup 1.0000x reference)
#include <cuda_runtime.h>
#include <math.h>
#include <cstdint>

#define B_   128
#define T_   512
#define D_   256
#define H_   512
#define G4_  2048   // 4*H

// ---- static device scratch ----
__device__ float g_xp[(size_t)T_ * B_ * G4_];     // [T*B, 4H] x-projections (+biases)
__device__ float g_h[2][B_ * H_];                 // ping-pong h, paired-fragment layout per row
__device__ volatile unsigned g_flag[2][128];      // per-CTA step flags (zero-init, self-resetting)

// =====================================================================
// helpers
// =====================================================================
__device__ __forceinline__ float tf32r(float x) {
    float y; asm("cvt.rna.tf32.f32 %0, %1;" : "=f"(y) : "f"(x)); return y;
}
__device__ __forceinline__ uint32_t smem_u32(const void* p) {
    uint32_t a;
    asm("{ .reg .u64 t; cvta.to.shared.u64 t, %1; cvt.u32.u64 %0, t; }" : "=r"(a) : "l"(p));
    return a;
}
__device__ __forceinline__ void mma1688(float* c, const uint32_t* a, const uint32_t* b) {
    asm volatile(
        "mma.sync.aligned.m16n8k8.row.col.f32.tf32.tf32.f32 "
        "{%0,%1,%2,%3}, {%4,%5,%6,%7}, {%8,%9}, {%0,%1,%2,%3};"
        : "+f"(c[0]), "+f"(c[1]), "+f"(c[2]), "+f"(c[3])
        : "r"(a[0]), "r"(a[1]), "r"(a[2]), "r"(a[3]), "r"(b[0]), "r"(b[1]));
}
__device__ __forceinline__ float fcomp(const float4& v, int i) {
    return i == 0 ? v.x : (i == 1 ? v.y : (i == 2 ? v.z : v.w));
}

// =====================================================================
// Kernel 1: x_proj GEMM via tf32 mma (round-3 proven version, unchanged)
// =====================================================================
#define XA_STR 68
#define XB_STR 68
#define XP_SMEM ((128 * XA_STR + 64 * XB_STR) * 4)

__global__ void __launch_bounds__(256, 1) xproj_mma(
    const float* __restrict__ x,     // [B*T, D]
    const float* __restrict__ Wih,   // [4H, D]
    const float* __restrict__ bih,
    const float* __restrict__ bhh)
{
    extern __shared__ float sm[];
    float* Ash = sm;                   // [128][68]
    float* Bsh = sm + 128 * XA_STR;    // [64][68]

    const int tid  = threadIdx.x;
    const int wid  = tid >> 5;
    const int lane = tid & 31;
    const int g    = lane >> 2;
    const int tig  = lane & 3;
    const int wm   = wid & 3;
    const int wcol = (wid >> 2) * 32;

    const int mt = blockIdx.x >> 5;
    const int nt = blockIdx.x & 31;
    const int m0 = mt * 128;
    const int n0 = nt * 64;

    float c[2][4][4];
#pragma unroll
    for (int a = 0; a < 2; ++a)
#pragma unroll
        for (int b = 0; b < 4; ++b)
#pragma unroll
            for (int i = 0; i < 4; ++i) c[a][b][i] = 0.f;

    for (int kc = 0; kc < 4; ++kc) {
        const int k0 = kc * 64;
        __syncthreads();
        {
            int row = tid >> 1;
            int h   = (tid & 1) * 32;
            const float* src = x + (size_t)(m0 + row) * D_ + k0 + h;
            float* dst = Ash + row * XA_STR + h;
#pragma unroll
            for (int i = 0; i < 8; ++i) {
                float4 v = *(const float4*)(src + i * 4);
                v.x = tf32r(v.x); v.y = tf32r(v.y); v.z = tf32r(v.z); v.w = tf32r(v.w);
                *(float4*)(dst + i * 4) = v;
            }
        }
        {
            int n = tid >> 2;
            int h = (tid & 3) * 16;
            const float* src = Wih + (size_t)(n0 + n) * D_ + k0 + h;
            float* dst = Bsh + n * XB_STR + h;
#pragma unroll
            for (int i = 0; i < 4; ++i) {
                float4 v = *(const float4*)(src + i * 4);
                v.x = tf32r(v.x); v.y = tf32r(v.y); v.z = tf32r(v.z); v.w = tf32r(v.w);
                *(float4*)(dst + i * 4) = v;
            }
        }
        __syncthreads();

        const float* a0p = Ash + (wm * 32 + g) * XA_STR;
        const float* a1p = a0p + 8 * XA_STR;
        const float* a2p = a0p + 16 * XA_STR;
        const float* a3p = a0p + 24 * XA_STR;
        const float* bp0 = Bsh + (wcol + 0  + g) * XB_STR;
        const float* bp1 = Bsh + (wcol + 8  + g) * XB_STR;
        const float* bp2 = Bsh + (wcol + 16 + g) * XB_STR;
        const float* bp3 = Bsh + (wcol + 24 + g) * XB_STR;

#pragma unroll 4
        for (int kk = 0; kk < 8; ++kk) {
            const int k8 = kk * 8 + tig;
            uint32_t af0[4] = { __float_as_uint(a0p[k8]), __float_as_uint(a1p[k8]),
                                __float_as_uint(a0p[k8 + 4]), __float_as_uint(a1p[k8 + 4]) };
            uint32_t af1[4] = { __float_as_uint(a2p[k8]), __float_as_uint(a3p[k8]),
                                __float_as_uint(a2p[k8 + 4]), __float_as_uint(a3p[k8 + 4]) };
            uint32_t bf0[2] = { __float_as_uint(bp0[k8]), __float_as_uint(bp0[k8 + 4]) };
            uint32_t bf1[2] = { __float_as_uint(bp1[k8]), __float_as_uint(bp1[k8 + 4]) };
            uint32_t bf2[2] = { __float_as_uint(bp2[k8]), __float_as_uint(bp2[k8 + 4]) };
            uint32_t bf3[2] = { __float_as_uint(bp3[k8]), __float_as_uint(bp3[k8 + 4]) };
            mma1688(c[0][0], af0, bf0); mma1688(c[0][1], af0, bf1);
            mma1688(c[0][2], af0, bf2); mma1688(c[0][3], af0, bf3);
            mma1688(c[1][0], af1, bf0); mma1688(c[1][1], af1, bf1);
            mma1688(c[1][2], af1, bf2); mma1688(c[1][3], af1, bf3);
        }
    }

    float2 bias[4];
#pragma unroll
    for (int nf = 0; nf < 4; ++nf) {
        int col = n0 + wcol + nf * 8 + 2 * tig;
        bias[nf].x = bih[col] + bhh[col];
        bias[nf].y = bih[col + 1] + bhh[col + 1];
    }
#pragma unroll
    for (int mf = 0; mf < 2; ++mf) {
#pragma unroll
        for (int rs = 0; rs < 2; ++rs) {
            int grow = m0 + wm * 32 + mf * 16 + g + rs * 8;
            int b = grow >> 9;
            int t = grow & 511;
            float* orow = g_xp + ((size_t)t * B_ + b) * G4_ + n0 + wcol + 2 * tig;
#pragma unroll
            for (int nf = 0; nf < 4; ++nf) {
                float2 v;
                v.x = c[mf][nf][rs * 2 + 0] + bias[nf].x;
                v.y = c[mf][nf][rs * 2 + 1] + bias[nf].y;
                *(float2*)(orow + nf * 8) = v;
            }
        }
    }
}

// =====================================================================
// Kernel 2: persistent recurrence v4 (round-3 skeleton + two fixes).
// =====================================================================
#define WSTR 528
#define HSH_OFF (64 * WSTR)
#define GSH_OFF (96 * WSTR)
#define REC_SMEM ((96 * WSTR + 32 * 68) * 4)    // 211456 B

__global__ void __launch_bounds__(256, 1) lstm_rec_mma(
    const float* __restrict__ Whh,   // [4H, H]
    float* __restrict__ out)         // [T*B, H]
{
    extern __shared__ float sm[];
    float* Wsh = sm;                  // [64 n][528] paired
    float* Hsh = sm + HSH_OFF;        // [32 b][528] paired
    float* Gsh = sm + GSH_OFF;        // [32 b][68]
    const uint32_t sb = smem_u32(sm);

    const int tid  = threadIdx.x;
    const int wid  = tid >> 5;
    const int lane = tid & 31;
    const int g    = lane >> 2;       // 0..7
    const int tq   = lane & 3;        // 0..3
    const int bt = blockIdx.x >> 5;
    const int jt = blockIdx.x & 31;
    const int b0 = bt * 32;
    const int j0 = jt * 16;
    const int cta = blockIdx.x;

    // ---- one-time: pack W_hh slice [64 n][512 k] into paired SMEM (row n = gate*16+jl) ----
    {
        int n    = tid >> 2;
        int kseg = (tid & 3) * 128;
        int gate = n >> 4, jl = n & 15;
        const float* src = Whh + (size_t)(gate * H_ + j0 + jl) * H_ + kseg;
        float* dst = Wsh + n * WSTR;
#pragma unroll 8
        for (int k = 0; k < 128; k += 4) {
            float4 v = *(const float4*)(src + k);
            int ka  = kseg + k;
            int base = (ka >> 4) * 16;
            int e   = ((ka >> 2) & 1) + 2 * ((ka >> 3) & 1);
            dst[base + 0  + e] = tf32r(v.x);
            dst[base + 4  + e] = tf32r(v.y);
            dst[base + 8  + e] = tf32r(v.z);
            dst[base + 12 + e] = tf32r(v.w);
        }
    }
    __syncthreads();

    const int q = wid;                // compute warps 0-3: gate index

    // cell ownership: 2 elements per thread
    const int eb = tid >> 3;          // 0..31
    const int ej = (tid * 2) & 15;    // even local j
    float c_reg[2] = {0.f, 0.f};

    // staging mapping: warp wid rows wid*4+rr; lane: block (lane>>2)+8*ii, chunk lane&3
    const int srow0 = wid * 4;
    const int sblk  = lane >> 2;
    const int sc    = lane & 3;

    // xp prefetch regs (compute warps): acc-init for current t
    float pf[2][2][4];
    if (wid < 4) {
        const float* xb = g_xp + (size_t)b0 * G4_ + q * 512 + j0 + 2 * tq;
#pragma unroll
        for (int m = 0; m < 2; ++m)
#pragma unroll
            for (int rs = 0; rs < 2; ++rs) {
                const float* r = xb + (size_t)(m * 16 + g + rs * 8) * G4_;
#pragma unroll
                for (int f = 0; f < 2; ++f) {
                    float2 v = *(const float2*)(r + f * 8);
                    pf[m][f][rs * 2 + 0] = v.x;
                    pf[m][f][rs * 2 + 1] = v.y;
                }
            }
    }

    for (int t = 0; t < T_; ++t) {
        if (t > 0) {
            // ---- A. poll bt group's 32 flags (warp 0; one 128B line) ----
            if (wid == 0) {
                volatile unsigned* f = &g_flag[(t - 1) & 1][bt * 32 + lane];
                while (*f < (unsigned)t) { }
                __threadfence();
            }
            __syncthreads();
            // ---- B. stage h_{t-1} into Hsh (cp.async.cg) ----
            {
                const float* hb = g_h[(t - 1) & 1];
#pragma unroll
                for (int rr = 0; rr < 4; ++rr) {
                    int row = srow0 + rr;
                    const float* src = hb + (size_t)(b0 + row) * 512;
                    uint32_t dst = sb + (uint32_t)(HSH_OFF + row * WSTR) * 4;
#pragma unroll
                    for (int ii = 0; ii < 4; ++ii) {
                        int off = (sblk + 8 * ii) * 16 + sc * 4;
                        asm volatile("cp.async.cg.shared.global [%0], [%1], 16;"
                                     :: "r"(dst + (uint32_t)off * 4), "l"(src + off));
                    }
                }
                asm volatile("cp.async.commit_group;" ::: "memory");
                asm volatile("cp.async.wait_group 0;" ::: "memory");
            }
        }
        __syncthreads();

        // ---- C. compute warps: acc init from xp, mma over K=512, store Gsh ----
        if (wid < 4) {
            float acc[2][2][4];
#pragma unroll
            for (int m = 0; m < 2; ++m)
#pragma unroll
                for (int f = 0; f < 2; ++f)
#pragma unroll
                    for (int i = 0; i < 4; ++i) acc[m][f][i] = pf[m][f][i];

            if (t > 0) {
                const float* Ha = Hsh + g * WSTR + tq * 4;
                const float* Wb = Wsh + (q * 16 + g) * WSTR + tq * 4;
#pragma unroll 4
                for (int z = 0; z < 32; ++z) {
                    const int offz = z * 16;
                    float4 a4[4];
#pragma unroll
                    for (int r = 0; r < 4; ++r)
                        a4[r] = *(const float4*)(Ha + r * 8 * WSTR + offz);
                    float4 b4[2];
#pragma unroll
                    for (int f = 0; f < 2; ++f)
                        b4[f] = *(const float4*)(Wb + f * 8 * WSTR + offz);
#pragma unroll
                    for (int s2 = 0; s2 < 2; ++s2) {
#pragma unroll
                        for (int m = 0; m < 2; ++m) {
                            uint32_t aa[4] = {
                                __float_as_uint(fcomp(a4[2 * m],     2 * s2)),
                                __float_as_uint(fcomp(a4[2 * m + 1], 2 * s2)),
                                __float_as_uint(fcomp(a4[2 * m],     2 * s2 + 1)),
                                __float_as_uint(fcomp(a4[2 * m + 1], 2 * s2 + 1)) };
#pragma unroll
                            for (int f = 0; f < 2; ++f) {
                                uint32_t bb[2] = {
                                    __float_as_uint(fcomp(b4[f], 2 * s2)),
                                    __float_as_uint(fcomp(b4[f], 2 * s2 + 1)) };
                                mma1688(acc[m][f], aa, bb);
                            }
                        }
                    }
                }
            }
#pragma unroll
            for (int m = 0; m < 2; ++m)
#pragma unroll
                for (int rs = 0; rs < 2; ++rs) {
                    float* gr = Gsh + (m * 16 + g + rs * 8) * 68 + q * 16 + 2 * tq;
#pragma unroll
                    for (int f = 0; f < 2; ++f) {
                        float2 v;
                        v.x = acc[m][f][rs * 2 + 0];
                        v.y = acc[m][f][rs * 2 + 1];
                        *(float2*)(gr + f * 8) = v;
                    }
                }
        }
        __syncthreads();

        // ---- D. prefetch xp for t+1 (overlaps cell) ----
        if (wid < 4 && t + 1 < T_) {
            const float* xb = g_xp + ((size_t)(t + 1) * B_ + b0) * G4_ + q * 512 + j0 + 2 * tq;
#pragma unroll
            for (int m = 0; m < 2; ++m)
#pragma unroll
                for (int rs = 0; rs < 2; ++rs) {
                    const float* r = xb + (size_t)(m * 16 + g + rs * 8) * G4_;
#pragma unroll
                    for (int f = 0; f < 2; ++f) {
                        float2 v = *(const float2*)(r + f * 8);
                        pf[m][f][rs * 2 + 0] = v.x;
                        pf[m][f][rs * 2 + 1] = v.y;
                    }
                }
        }

        // ---- E. cell: 2 elements per thread ----
        {
            const float* gr = Gsh + eb * 68;
            float* hrow = g_h[t & 1] + (size_t)(b0 + eb) * 512;
            float* orow = out + ((size_t)t * B_ + b0 + eb) * H_ + j0;
#pragma unroll
            for (int p = 0; p < 2; ++p) {
                int jl = ej + p;
                float gi = gr[0  + jl];
                float gf = gr[16 + jl];
                float gg = gr[32 + jl];
                float go = gr[48 + jl];
                float i_s = 1.f / (1.f + __expf(-gi));
                float f_s = 1.f / (1.f + __expf(-gf));
                float o_s = 1.f / (1.f + __expf(-go));
                float g_t = tanhf(gg);
                float cv  = f_s * c_reg[p] + i_s * g_t;
                c_reg[p]  = cv;
                float hv  = o_s * tanhf(cv);
                orow[jl] = hv;
                int pos = jt * 16 + (jl & 3) * 4 + ((jl >> 2) & 1) + 2 * ((jl >> 3) & 1);
                hrow[pos] = tf32r(hv);
            }
        }
        __threadfence();
        __syncthreads();

        // ---- F. signal step complete ----
        if (tid == 0) g_flag[t & 1][cta] = (unsigned)(t + 1);
    }

    // ---- final: wait for everyone, then reset flags (graph-replay safe) ----
    if (wid < 4) {
        volatile unsigned* f = &g_flag[1][wid * 32 + lane];
        while (*f < (unsigned)T_) { }
    }
    __syncthreads();
    if (tid == 0) { g_flag[0][cta] = 0; g_flag[1][cta] = 0; }
}

// =====================================================================
extern "C" void kernel_launch(void* const* d_in, const int* in_sizes, int n_in,
                              void* d_out, int out_size)
{
    const float* x   = (const float*)d_in[0];   // [B,T,D]
    const float* Wih = (const float*)d_in[1];   // [4H,D]
    const float* Whh = (const float*)d_in[2];   // [4H,H]
    const float* bih = (const float*)d_in[3];   // [4H]
    const float* bhh = (const float*)d_in[4];   // [4H]
    float* out = (float*)d_out;

    cudaFuncSetAttribute(xproj_mma,
                         cudaFuncAttributeMaxDynamicSharedMemorySize, XP_SMEM);
    xproj_mma<<<16384, 256, XP_SMEM>>>(x, Wih, bih, bhh);

    cudaFuncSetAttribute(lstm_rec_mma,
                         cudaFuncAttributeMaxDynamicSharedMemorySize, REC_SMEM);
    lstm_rec_mma<<<128, 256, REC_SMEM>>>(Whh, out);
}